// round 10
// baseline (speedup 1.0000x reference)
#include <cuda_runtime.h>
#include <cuda_bf16.h>

// Problem constants (fixed shapes)
#define BATCH 4096
#define DIN   2048
#define DHID  16384
#define KDIM  4096   // 2*DIN
#define TOPK  64

// ---------------------------------------------------------------------------
// Device scratch (__device__ globals; NEVER passed as kernel args from host —
// host-side symbol decay gives the host shadow address, which on GB300 (ATS)
// is silently writable and was the root cause of the R5-R8 zero outputs).
// g_pre doubles as the z fallback when d_out has no room for z (safe: each
// topk CTA fully consumes its pre row before overwriting it).
// ---------------------------------------------------------------------------
__device__ float g_X  [(size_t)BATCH * KDIM];   //  64 MB concat input
__device__ float g_pre[(size_t)BATCH * DHID];   // 256 MB encoder out / z fallback
__device__ float g_WmT[(size_t)DHID * DIN];     // 128 MB W_dec_m^T
__device__ float g_WpT[(size_t)DHID * DIN];     // 128 MB W_dec_p^T
__device__ float g_dump[(size_t)BATCH * DIN];   //  33 MB rec_p fallback
__device__ int   g_sel_idx[(size_t)BATCH * TOPK];
__device__ float g_sel_val[(size_t)BATCH * TOPK];

// ---------------------------------------------------------------------------
// 1) Concat x_m | x_p  ->  g_X   (float4 grid)
// ---------------------------------------------------------------------------
__global__ void concat_kernel(const float4* __restrict__ xm,
                              const float4* __restrict__ xp) {
    int i = blockIdx.x * blockDim.x + threadIdx.x;   // over BATCH * KDIM/4
    int row = i >> 10;           // KDIM/4 = 1024
    int c4  = i & 1023;
    float4 v = (c4 < 512) ? xm[(size_t)row * 512 + c4]
                          : xp[(size_t)row * 512 + (c4 - 512)];
    ((float4*)g_X)[i] = v;
}

// ---------------------------------------------------------------------------
// 2) SGEMM (NT):  g_pre[M,N] = g_X[M,K] * W[N,K]^T + bias[N]
//    128x128x16 tile, 256 threads, 8x8 per thread, fp32.
// ---------------------------------------------------------------------------
#define BM 128
#define BN 128
#define BKK 16

__global__ __launch_bounds__(256) void sgemm_kernel(const float* __restrict__ Wn,
                                                    const float* __restrict__ bias) {
    __shared__ float As[BKK][BM + 4];
    __shared__ float Bs[BKK][BN + 4];

    const float* A = g_X;
    int bm = blockIdx.y * BM;
    int bn = blockIdx.x * BN;
    int tid = threadIdx.x;
    int tx = tid & 15;          // 0..15  -> N direction (8 cols each)
    int ty = tid >> 4;          // 0..15  -> M direction (8 rows each)

    float acc[8][8];
    #pragma unroll
    for (int i = 0; i < 8; i++)
        #pragma unroll
        for (int j = 0; j < 8; j++) acc[i][j] = 0.0f;

    int lrow = tid >> 2;          // 0..63
    int lcol = (tid & 3) << 2;    // 0,4,8,12

    for (int k0 = 0; k0 < KDIM; k0 += BKK) {
        #pragma unroll
        for (int r = 0; r < 2; r++) {
            int m = lrow + 64 * r;
            float4 va = *(const float4*)(A  + (size_t)(bm + m) * KDIM + k0 + lcol);
            As[lcol + 0][m] = va.x; As[lcol + 1][m] = va.y;
            As[lcol + 2][m] = va.z; As[lcol + 3][m] = va.w;
            float4 vb = *(const float4*)(Wn + (size_t)(bn + m) * KDIM + k0 + lcol);
            Bs[lcol + 0][m] = vb.x; Bs[lcol + 1][m] = vb.y;
            Bs[lcol + 2][m] = vb.z; Bs[lcol + 3][m] = vb.w;
        }
        __syncthreads();

        #pragma unroll
        for (int kk = 0; kk < BKK; kk++) {
            float a[8], b[8];
            *(float4*)&a[0] = *(const float4*)&As[kk][ty * 8];
            *(float4*)&a[4] = *(const float4*)&As[kk][ty * 8 + 4];
            *(float4*)&b[0] = *(const float4*)&Bs[kk][tx * 8];
            *(float4*)&b[4] = *(const float4*)&Bs[kk][tx * 8 + 4];
            #pragma unroll
            for (int i = 0; i < 8; i++)
                #pragma unroll
                for (int j = 0; j < 8; j++)
                    acc[i][j] += a[i] * b[j];
        }
        __syncthreads();
    }

    #pragma unroll
    for (int i = 0; i < 8; i++) {
        size_t off = (size_t)(bm + ty * 8 + i) * DHID + bn + tx * 8;
        #pragma unroll
        for (int j = 0; j < 8; j++)
            g_pre[off + j] = acc[i][j] + bias[bn + tx * 8 + j];
    }
}

// ---------------------------------------------------------------------------
// 3) Transpose W_dec [DIN, DHID] -> g_WmT / g_WpT [DHID, DIN].
//    Destination selected by flag IN DEVICE CODE (the R5-R8 bug fix).
// ---------------------------------------------------------------------------
__global__ void transpose_kernel(const float* __restrict__ in, int which) {
    float* out = which ? g_WpT : g_WmT;
    const int R = DIN, C = DHID;
    __shared__ float tile[32][33];
    int c0 = blockIdx.x * 32, r0 = blockIdx.y * 32;
    int tx = threadIdx.x, ty = threadIdx.y;
    #pragma unroll
    for (int j = 0; j < 32; j += 8)
        tile[ty + j][tx] = in[(size_t)(r0 + ty + j) * C + c0 + tx];
    __syncthreads();
    #pragma unroll
    for (int j = 0; j < 32; j += 8)
        out[(size_t)(c0 + ty + j) * R + r0 + tx] = tile[tx][ty + j];
}

// ---------------------------------------------------------------------------
// 4) Per-row exact top-64.
//    Candidate collection (> 2.0, retry > 1.0, bitmask full-scan fallback),
//    then 64 argmax rounds with (value, lower-index) ordering == jax.lax.top_k.
// ---------------------------------------------------------------------------
#define CAP 2048

__device__ __forceinline__ unsigned long long tk_pack(float v, int idx) {
    unsigned int u = __float_as_uint(v);
    u = (u & 0x80000000u) ? ~u : (u | 0x80000000u);   // order-preserving flip
    return ((unsigned long long)u << 32) | (unsigned int)(DHID - 1 - idx);
}

__global__ __launch_bounds__(256) void topk_kernel(float* __restrict__ z_out,
                                                   int z_in_out) {
    int row = blockIdx.x, tid = threadIdx.x;
    const float* p = g_pre + (size_t)row * DHID;
    float* zr = (z_in_out ? z_out : g_pre) + (size_t)row * DHID;

    __shared__ float cv[CAP];
    __shared__ int   ci[CAP];
    __shared__ int   s_cnt;
    __shared__ unsigned long long s_red[8];
    __shared__ unsigned long long s_win;
    __shared__ unsigned int selmask[DHID / 32];   // 2 KB
    __shared__ int   s_seli[TOPK];
    __shared__ float s_selv[TOPK];

    const float thr[2] = {2.0f, 1.0f};
    int cnt = -1;
    for (int t = 0; t < 2; t++) {
        if (tid == 0) s_cnt = 0;
        __syncthreads();
        for (int i = tid; i < DHID; i += 256) {
            float v = p[i];
            if (v > thr[t]) {
                int pos = atomicAdd(&s_cnt, 1);
                if (pos < CAP) { cv[pos] = v; ci[pos] = i; }
            }
        }
        __syncthreads();
        cnt = s_cnt;
        __syncthreads();
        if (cnt >= TOPK && cnt <= CAP) break;
        if (t == 0 && cnt > CAP) { cnt = -1; break; }  // too many at 2.0 -> full scan
    }
    bool fb = !(cnt >= TOPK && cnt <= CAP);   // statistically ~never taken
    if (fb) {
        for (int i = tid; i < DHID / 32; i += 256) selmask[i] = 0u;
        __syncthreads();
    }

    for (int r = 0; r < TOPK; r++) {
        unsigned long long best = 0ull;
        if (!fb) {
            for (int c = tid; c < cnt; c += 256) {
                unsigned long long k2 = tk_pack(cv[c], ci[c]);
                if (k2 > best) best = k2;
            }
        } else {
            for (int i = tid; i < DHID; i += 256) {
                if (selmask[i >> 5] & (1u << (i & 31))) continue;
                unsigned long long k2 = tk_pack(p[i], i);
                if (k2 > best) best = k2;
            }
        }
        #pragma unroll
        for (int o = 16; o > 0; o >>= 1) {
            unsigned long long other = __shfl_xor_sync(0xffffffffu, best, o);
            if (other > best) best = other;
        }
        if ((tid & 31) == 0) s_red[tid >> 5] = best;
        __syncthreads();
        if (tid == 0) {
            unsigned long long w = s_red[0];
            #pragma unroll
            for (int i = 1; i < 8; i++)
                if (s_red[i] > w) w = s_red[i];
            s_win = w;
        }
        __syncthreads();
        unsigned long long w = s_win;
        int fidx = (DHID - 1) - (int)(w & 0xffffffffull);
        if (tid == 0) {
            unsigned int u = (unsigned int)(w >> 32);
            u = (u & 0x80000000u) ? (u & 0x7fffffffu) : ~u;
            float fv = __uint_as_float(u);
            s_seli[r] = fidx;
            s_selv[r] = fmaxf(fv, 0.0f);   // relu
        }
        if (!fb) {
            for (int c = tid; c < cnt; c += 256)
                if (ci[c] == fidx) cv[c] = -3.0e38f;
        } else {
            if (tid == 0) selmask[fidx >> 5] |= (1u << (fidx & 31));
        }
        __syncthreads();
    }

    // compact selection first (decode depends only on these)
    if (tid < TOPK) {
        g_sel_idx[(size_t)row * TOPK + tid] = s_seli[tid];
        g_sel_val[(size_t)row * TOPK + tid] = s_selv[tid];
    }
    __syncthreads();

    // dense z row: zeros + scatter
    for (int i = tid; i < DHID; i += 256) zr[i] = 0.0f;
    __syncthreads();
    if (tid < TOPK) zr[s_seli[tid]] = s_selv[tid];
}

// ---------------------------------------------------------------------------
// 5) Sparse decode: one CTA per batch row. rec = sum_j val_j * WT[idx_j, :]
// ---------------------------------------------------------------------------
__device__ __forceinline__ void fma4(float4& acc, float v, float4 w) {
    acc.x += v * w.x; acc.y += v * w.y; acc.z += v * w.z; acc.w += v * w.w;
}

__global__ __launch_bounds__(256) void decode_kernel(float* __restrict__ rec_m,
                                                     float* __restrict__ rec_p,
                                                     int p_in_out) {
    int row = blockIdx.x, tid = threadIdx.x;
    __shared__ int   si[TOPK];
    __shared__ float sv[TOPK];
    if (tid < TOPK) {
        si[tid] = g_sel_idx[(size_t)row * TOPK + tid];
        sv[tid] = g_sel_val[(size_t)row * TOPK + tid];
    }
    __syncthreads();

    float4 am0 = {0.f, 0.f, 0.f, 0.f}, am1 = am0, ap0 = am0, ap1 = am0;

    #pragma unroll 4
    for (int j = 0; j < TOPK; j++) {
        float v = sv[j];
        size_t base = (size_t)si[j] * DIN;
        const float4* wm = (const float4*)(g_WmT + base);
        const float4* wp = (const float4*)(g_WpT + base);
        float4 a0 = wm[tid], a1 = wm[tid + 256];
        float4 b0 = wp[tid], b1 = wp[tid + 256];
        fma4(am0, v, a0); fma4(am1, v, a1);
        fma4(ap0, v, b0); fma4(ap1, v, b1);
    }

    float4* om = (float4*)(rec_m + (size_t)row * DIN);
    float* pp = p_in_out ? rec_p : g_dump;
    float4* op = (float4*)(pp + (size_t)row * DIN);
    om[tid] = am0; om[tid + 256] = am1;
    op[tid] = ap0; op[tid + 256] = ap1;
}

// ---------------------------------------------------------------------------
// Launch.  By-size input binding (unambiguous; m-before-p holds for both dict
// and alphabetical metadata orderings) + adaptive output layout (never write
// d_out beyond out_size).
// ---------------------------------------------------------------------------
extern "C" void kernel_launch(void* const* d_in, const int* in_sizes, int n_in,
                              void* d_out, int out_size) {
    const float* x_m = 0; const float* x_p = 0;
    const float* W_enc = 0; const float* b_enc = 0;
    const float* W_dec_m = 0; const float* W_dec_p = 0;

    for (int i = 0; i < n_in; i++) {
        long long s = in_sizes[i];
        const float* p = (const float*)d_in[i];
        if (s == (long long)BATCH * DIN) {            // 8,388,608
            if (!x_m) x_m = p; else x_p = p;
        } else if (s == (long long)DHID * KDIM) {     // 67,108,864
            W_enc = p;
        } else if (s == (long long)DHID) {            // 16,384
            b_enc = p;
        } else if (s == (long long)DIN * DHID) {      // 33,554,432
            if (!W_dec_m) W_dec_m = p; else W_dec_p = p;
        }
        // s == 1 -> k (always 64), ignored
    }
    if (!x_m || !x_p || !W_enc || !b_enc || !W_dec_m || !W_dec_p)
        return;   // binding failure -> 0 captured nodes -> distinct diagnostic

    const long long SZ_REC  = (long long)BATCH * DIN;                // 8,388,608
    const long long SZ_FULL = 2 * SZ_REC + (long long)BATCH * DHID;  // 83,886,080

    float* rec_m = (float*)d_out;
    float* rec_p = rec_m;
    float* z_ptr = rec_m;
    int p_in_out = 0, z_in_out = 0;

    if ((long long)out_size >= SZ_FULL) {
        rec_p = rec_m + SZ_REC; z_ptr = rec_p + SZ_REC;
        p_in_out = 1; z_in_out = 1;
    } else if ((long long)out_size >= 2 * SZ_REC) {
        rec_p = rec_m + SZ_REC;
        p_in_out = 1; z_in_out = 0;   // z -> g_pre fallback (in-device)
    } else {
        p_in_out = 0; z_in_out = 0;   // rec_p -> g_dump, z -> g_pre (in-device)
    }

    // 1) concat inputs
    concat_kernel<<<(BATCH * (KDIM / 4)) / 256, 256>>>((const float4*)x_m,
                                                       (const float4*)x_p);
    // 2) encoder GEMM (fp32)
    dim3 ggrid(DHID / BN, BATCH / BM);
    sgemm_kernel<<<ggrid, 256>>>(W_enc, b_enc);

    // 3) decoder transposes (dest chosen inside device code)
    dim3 tgrid(DHID / 32, DIN / 32), tblk(32, 8);
    transpose_kernel<<<tgrid, tblk>>>(W_dec_m, 0);
    transpose_kernel<<<tgrid, tblk>>>(W_dec_p, 1);

    // 4) top-k + z
    topk_kernel<<<BATCH, 256>>>(z_ptr, z_in_out);

    // 5) sparse decode
    decode_kernel<<<BATCH, 256>>>(rec_m, rec_p, p_in_out);
}

// round 15
// speedup vs baseline: 2.4002x; 2.4002x over previous
#include <cuda_runtime.h>
#include <cuda_bf16.h>
#include <cstdint>

// Problem constants (fixed shapes)
#define BATCH 4096
#define DIN   2048
#define DHID  16384
#define KDIM  4096   // 2*DIN
#define TOPK  64

// ---------------------------------------------------------------------------
// Device scratch (__device__ globals; never passed as kernel args from host)
// ---------------------------------------------------------------------------
__device__ float        g_X  [(size_t)BATCH * KDIM];   //  64 MB concat fp32 (for rescue)
__device__ __nv_bfloat16 g_Ahi[(size_t)BATCH * KDIM];  //  32 MB
__device__ __nv_bfloat16 g_Alo[(size_t)BATCH * KDIM];  //  32 MB
__device__ __nv_bfloat16 g_Bhi[(size_t)DHID * KDIM];   // 128 MB
__device__ __nv_bfloat16 g_Blo[(size_t)DHID * KDIM];   // 128 MB
__device__ float g_pre[(size_t)BATCH * DHID];          // 256 MB screen out / z fallback
__device__ float g_WmT[(size_t)DHID * DIN];            // 128 MB W_dec_m^T
__device__ float g_WpT[(size_t)DHID * DIN];            // 128 MB W_dec_p^T
__device__ float g_dump[(size_t)BATCH * DIN];          //  33 MB rec_p fallback
__device__ int   g_sel_idx[(size_t)BATCH * TOPK];
__device__ float g_sel_val[(size_t)BATCH * TOPK];

// ---------------------------------------------------------------------------
// PTX helpers — ONLY family-level instructions (sm_80+): compile on compute_103
// ---------------------------------------------------------------------------
__device__ __forceinline__ uint32_t smem_u32(const void* p) {
    uint32_t a;
    asm("{ .reg .u64 t; cvta.to.shared.u64 t, %1; cvt.u32.u64 %0, t; }"
        : "=r"(a) : "l"(p));
    return a;
}

__device__ __forceinline__ void cp16(uint32_t s, const void* g) {
    asm volatile("cp.async.cg.shared.global [%0], [%1], 16;"
                 :: "r"(s), "l"(g) : "memory");
}
#define CP_COMMIT() asm volatile("cp.async.commit_group;" ::: "memory")
#define CP_WAIT1()  asm volatile("cp.async.wait_group 1;" ::: "memory")
#define CP_WAIT0()  asm volatile("cp.async.wait_group 0;" ::: "memory")

#define LDSM4(r, addr) \
    asm volatile("ldmatrix.sync.aligned.m8n8.x4.shared.b16 {%0,%1,%2,%3}, [%4];" \
        : "=r"((r)[0]), "=r"((r)[1]), "=r"((r)[2]), "=r"((r)[3]) : "r"(addr))

#define MMA16816(d, a, b0, b1) \
    asm volatile("mma.sync.aligned.m16n8k16.row.col.f32.bf16.bf16.f32 " \
        "{%0,%1,%2,%3}, {%4,%5,%6,%7}, {%8,%9}, {%0,%1,%2,%3};" \
        : "+f"((d)[0]), "+f"((d)[1]), "+f"((d)[2]), "+f"((d)[3]) \
        : "r"((a)[0]), "r"((a)[1]), "r"((a)[2]), "r"((a)[3]), "r"(b0), "r"(b1))

// ---------------------------------------------------------------------------
// 1a) concat x -> g_X (fp32, for rescue) and split into bf16 hi/lo
// ---------------------------------------------------------------------------
__global__ void split_x_kernel(const float4* __restrict__ xm,
                               const float4* __restrict__ xp) {
    int i = blockIdx.x * blockDim.x + threadIdx.x;   // BATCH*KDIM/4
    int row = i >> 10, c4 = i & 1023;
    float4 v = (c4 < 512) ? xm[(size_t)row * 512 + c4]
                          : xp[(size_t)row * 512 + (c4 - 512)];
    ((float4*)g_X)[i] = v;
    float f[4] = {v.x, v.y, v.z, v.w};
    __nv_bfloat16 hx[4], lx[4];
    #pragma unroll
    for (int j = 0; j < 4; j++) {
        hx[j] = __float2bfloat16(f[j]);
        lx[j] = __float2bfloat16(f[j] - __bfloat162float(hx[j]));
    }
    __nv_bfloat162 h0, h1, l0, l1;
    h0.x = hx[0]; h0.y = hx[1]; h1.x = hx[2]; h1.y = hx[3];
    l0.x = lx[0]; l0.y = lx[1]; l1.x = lx[2]; l1.y = lx[3];
    ((__nv_bfloat162*)g_Ahi)[2 * i] = h0; ((__nv_bfloat162*)g_Ahi)[2 * i + 1] = h1;
    ((__nv_bfloat162*)g_Alo)[2 * i] = l0; ((__nv_bfloat162*)g_Alo)[2 * i + 1] = l1;
}

// 1b) split W_enc into bf16 hi/lo
__global__ void split_w_kernel(const float4* __restrict__ W) {
    int i = blockIdx.x * blockDim.x + threadIdx.x;   // DHID*KDIM/4
    float4 v = W[i];
    float f[4] = {v.x, v.y, v.z, v.w};
    __nv_bfloat16 hx[4], lx[4];
    #pragma unroll
    for (int j = 0; j < 4; j++) {
        hx[j] = __float2bfloat16(f[j]);
        lx[j] = __float2bfloat16(f[j] - __bfloat162float(hx[j]));
    }
    __nv_bfloat162 h0, h1, l0, l1;
    h0.x = hx[0]; h0.y = hx[1]; h1.x = hx[2]; h1.y = hx[3];
    l0.x = lx[0]; l0.y = lx[1]; l1.x = lx[2]; l1.y = lx[3];
    ((__nv_bfloat162*)g_Bhi)[2 * i] = h0; ((__nv_bfloat162*)g_Bhi)[2 * i + 1] = h1;
    ((__nv_bfloat162*)g_Blo)[2 * i] = l0; ((__nv_bfloat162*)g_Blo)[2 * i + 1] = l1;
}

// ---------------------------------------------------------------------------
// 2) mma.sync bf16 GEMM, 3-term split (hh + lh + hl), fp32 reg accumulators.
//    CTA tile 128x128, K-chunk 64, 2-stage cp.async double buffer.
//    8 warps = 4(M) x 2(N); warp tile 32x64.
//    SMEM rows padded to 144B -> conflict-free ldmatrix (quad = (r + s) % 8).
// ---------------------------------------------------------------------------
#define GK       64
#define NC       (KDIM / GK)              // 64 chunks
#define ROWB     144                      // 128B data + 16B pad
#define TILE_B   (128 * ROWB)             // 18432
#define STAGE_B  (4 * TILE_B)             // Ahi|Alo|Bhi|Blo = 73728
#define GEMM_DSMEM (2 * STAGE_B + 256)

__global__ __launch_bounds__(256, 1) void gemm_kernel(const float* __restrict__ bias) {
    extern __shared__ char dsm_raw[];
    uint32_t dyn = (smem_u32(dsm_raw) + 255) & ~255u;

    const int tid  = threadIdx.x;
    const int lane = tid & 31;
    const int wid  = tid >> 5;
    const int bm   = blockIdx.x * 128;    // M (fast grid dim -> B L2 reuse)
    const int bn   = blockIdx.y * 128;    // N
    const int wm   = (wid >> 1) * 32;     // warp M offset
    const int wn   = (wid & 1) * 64;      // warp N offset

    // ldmatrix per-thread row/offset pieces
    const uint32_t aRow = (uint32_t)(wm + (lane & 15));
    const uint32_t aKo  = (uint32_t)((lane >> 4) * 16);
    const uint32_t bRow = (uint32_t)(wn + (lane & 7) + ((lane >> 4) << 3));
    const uint32_t bKo  = (uint32_t)(((lane >> 3) & 1) * 16);

    float acc[2][8][4];
    #pragma unroll
    for (int mi = 0; mi < 2; mi++)
        #pragma unroll
        for (int ni = 0; ni < 8; ni++)
            #pragma unroll
            for (int q = 0; q < 4; q++) acc[mi][ni][q] = 0.0f;

    // chunk loader: 4 tiles x 128 rows x 128B via 16B cp.async
    const int lrow = tid >> 3;      // 0..31
    const int lseg = tid & 7;       // 0..7
    auto load_chunk = [&](int c) {
        const int kc = c * GK;
        const uint32_t sb = dyn + (uint32_t)(c & 1) * STAGE_B;
        #pragma unroll
        for (int tile = 0; tile < 4; tile++) {
            const __nv_bfloat16* src =
                (tile == 0) ? g_Ahi : (tile == 1) ? g_Alo :
                (tile == 2) ? g_Bhi : g_Blo;
            const int base = (tile < 2) ? bm : bn;
            #pragma unroll
            for (int p = 0; p < 4; p++) {
                const int r = lrow + p * 32;
                cp16(sb + (uint32_t)tile * TILE_B + (uint32_t)r * ROWB + (uint32_t)lseg * 16,
                     src + (size_t)(base + r) * KDIM + kc + lseg * 8);
            }
        }
        CP_COMMIT();
    };

    load_chunk(0);
    load_chunk(1);

    for (int c = 0; c < NC; c++) {
        if (c < NC - 2) CP_WAIT1(); else CP_WAIT0();
        __syncthreads();

        const uint32_t sb = dyn + (uint32_t)(c & 1) * STAGE_B;
        #pragma unroll
        for (int kk = 0; kk < 4; kk++) {
            const uint32_t kby = (uint32_t)kk * 32;
            uint32_t ah[2][4], al[2][4], bh[4][4], bl[4][4];
            #pragma unroll
            for (int mi = 0; mi < 2; mi++) {
                uint32_t ra = sb + (aRow + (uint32_t)mi * 16) * ROWB + kby + aKo;
                LDSM4(ah[mi], ra);
                LDSM4(al[mi], ra + TILE_B);
            }
            #pragma unroll
            for (int g = 0; g < 4; g++) {
                uint32_t rb = sb + 2u * TILE_B + (bRow + (uint32_t)g * 16) * ROWB + kby + bKo;
                LDSM4(bh[g], rb);
                LDSM4(bl[g], rb + TILE_B);
            }
            // term hh
            #pragma unroll
            for (int mi = 0; mi < 2; mi++)
                #pragma unroll
                for (int ni = 0; ni < 8; ni++)
                    MMA16816(acc[mi][ni], ah[mi],
                             bh[ni >> 1][(ni & 1) * 2], bh[ni >> 1][(ni & 1) * 2 + 1]);
            // term lh
            #pragma unroll
            for (int mi = 0; mi < 2; mi++)
                #pragma unroll
                for (int ni = 0; ni < 8; ni++)
                    MMA16816(acc[mi][ni], al[mi],
                             bh[ni >> 1][(ni & 1) * 2], bh[ni >> 1][(ni & 1) * 2 + 1]);
            // term hl
            #pragma unroll
            for (int mi = 0; mi < 2; mi++)
                #pragma unroll
                for (int ni = 0; ni < 8; ni++)
                    MMA16816(acc[mi][ni], ah[mi],
                             bl[ni >> 1][(ni & 1) * 2], bl[ni >> 1][(ni & 1) * 2 + 1]);
        }
        __syncthreads();
        if (c + 2 < NC) load_chunk(c + 2);
    }

    // epilogue: direct float2 stores + bias
    #pragma unroll
    for (int mi = 0; mi < 2; mi++) {
        const int m0 = bm + wm + mi * 16 + (lane >> 2);
        #pragma unroll
        for (int ni = 0; ni < 8; ni++) {
            const int n = bn + wn + ni * 8 + ((lane & 3) << 1);
            const float b0 = bias[n], b1 = bias[n + 1];
            float2 v0 = make_float2(acc[mi][ni][0] + b0, acc[mi][ni][1] + b1);
            float2 v1 = make_float2(acc[mi][ni][2] + b0, acc[mi][ni][3] + b1);
            *(float2*)(g_pre + (size_t)m0 * DHID + n)       = v0;
            *(float2*)(g_pre + (size_t)(m0 + 8) * DHID + n) = v1;
        }
    }
}

// ---------------------------------------------------------------------------
// 3) Transpose W_dec [DIN, DHID] -> g_WmT / g_WpT (dest flag in device code)
// ---------------------------------------------------------------------------
__global__ void transpose_kernel(const float* __restrict__ in, int which) {
    float* out = which ? g_WpT : g_WmT;
    const int R = DIN, C = DHID;
    __shared__ float tile[32][33];
    int c0 = blockIdx.x * 32, r0 = blockIdx.y * 32;
    int tx = threadIdx.x, ty = threadIdx.y;
    #pragma unroll
    for (int j = 0; j < 32; j += 8)
        tile[ty + j][tx] = in[(size_t)(r0 + ty + j) * C + c0 + tx];
    __syncthreads();
    #pragma unroll
    for (int j = 0; j < 32; j += 8)
        out[(size_t)(c0 + ty + j) * R + r0 + tx] = tile[tx][ty + j];
}

// ---------------------------------------------------------------------------
// 4) Per-row top-64 on the SCREEN with exact-fp32 boundary rescue.
//    65 argmax rounds; rows whose 64/65 screen gap > 2*EMAX are provably
//    exact; otherwise ambiguous candidates get exact fp32 dot rescore.
// ---------------------------------------------------------------------------
#define CAP 2048
#define RROUNDS 65
#define EMAX 2.0e-4f
#define AMBMAX 96

__device__ __forceinline__ unsigned long long tk_pack(float v, int idx) {
    unsigned int u = __float_as_uint(v);
    u = (u & 0x80000000u) ? ~u : (u | 0x80000000u);
    return ((unsigned long long)u << 32) | (unsigned int)(DHID - 1 - idx);
}

__global__ __launch_bounds__(256) void topk_kernel(float* __restrict__ z_out,
                                                   int z_in_out,
                                                   const float* __restrict__ Wenc,
                                                   const float* __restrict__ benc) {
    int row = blockIdx.x, tid = threadIdx.x;
    const float* p = g_pre + (size_t)row * DHID;
    float* zr = (z_in_out ? z_out : g_pre) + (size_t)row * DHID;

    __shared__ float cv[CAP];
    __shared__ int   ci[CAP];
    __shared__ int   s_cnt;
    __shared__ unsigned long long s_red[8];
    __shared__ unsigned long long s_win;
    __shared__ unsigned int selmask[DHID / 32];
    __shared__ int   s_seli[RROUNDS];
    __shared__ float s_rawv[RROUNDS];
    __shared__ int   s_ambi[AMBMAX];
    __shared__ float s_ambx[AMBMAX];
    __shared__ int   s_na, s_m;
    __shared__ float s_part[8];

    const float thr[2] = {2.0f, 1.0f};
    int cnt = -1;
    for (int t = 0; t < 2; t++) {
        if (tid == 0) s_cnt = 0;
        __syncthreads();
        for (int i = tid; i < DHID; i += 256) {
            float v = p[i];
            if (v > thr[t]) {
                int pos = atomicAdd(&s_cnt, 1);
                if (pos < CAP) { cv[pos] = v; ci[pos] = i; }
            }
        }
        __syncthreads();
        cnt = s_cnt;
        __syncthreads();
        if (cnt >= RROUNDS && cnt <= CAP) break;
        if (t == 0 && cnt > CAP) { cnt = -1; break; }
    }
    bool fb = !(cnt >= RROUNDS && cnt <= CAP);
    if (fb) {
        for (int i = tid; i < DHID / 32; i += 256) selmask[i] = 0u;
        __syncthreads();
    }

    for (int r = 0; r < RROUNDS; r++) {
        unsigned long long best = 0ull;
        if (!fb) {
            for (int c = tid; c < cnt; c += 256) {
                unsigned long long k2 = tk_pack(cv[c], ci[c]);
                if (k2 > best) best = k2;
            }
        } else {
            for (int i = tid; i < DHID; i += 256) {
                if (selmask[i >> 5] & (1u << (i & 31))) continue;
                unsigned long long k2 = tk_pack(p[i], i);
                if (k2 > best) best = k2;
            }
        }
        #pragma unroll
        for (int o = 16; o > 0; o >>= 1) {
            unsigned long long other = __shfl_xor_sync(0xffffffffu, best, o);
            if (other > best) best = other;
        }
        if ((tid & 31) == 0) s_red[tid >> 5] = best;
        __syncthreads();
        if (tid == 0) {
            unsigned long long w = s_red[0];
            #pragma unroll
            for (int i = 1; i < 8; i++)
                if (s_red[i] > w) w = s_red[i];
            s_win = w;
        }
        __syncthreads();
        unsigned long long w = s_win;
        int fidx = (DHID - 1) - (int)(w & 0xffffffffull);
        if (tid == 0) {
            unsigned int u = (unsigned int)(w >> 32);
            u = (u & 0x80000000u) ? (u & 0x7fffffffu) : ~u;
            s_seli[r] = fidx;
            s_rawv[r] = __uint_as_float(u);   // raw (pre-relu) value
        }
        if (!fb) {
            for (int c = tid; c < cnt; c += 256)
                if (ci[c] == fidx) cv[c] = -3.0e38f;
        } else {
            if (tid == 0) selmask[fidx >> 5] |= (1u << (fidx & 31));
        }
        __syncthreads();
    }

    // ---- exactness rescue ----
    if (tid == 0) {
        float S65 = s_rawv[RROUNDS - 1];
        int m = 0;
        while (m < TOPK && s_rawv[m] > S65 + 2.0f * EMAX) m++;
        s_m = m;
    }
    __syncthreads();
    int m = s_m;

    if (!fb && m < TOPK) {
        if (tid == 0) s_na = 0;
        __syncthreads();
        float lo = s_rawv[RROUNDS - 1] - 2.0f * EMAX;
        if (tid <= (RROUNDS - 1) - m) {            // ranked m..64
            int pos = atomicAdd(&s_na, 1);
            if (pos < AMBMAX) s_ambi[pos] = s_seli[m + tid];
        }
        for (int c = tid; c < cnt; c += 256) {     // unranked near-boundary
            if (cv[c] >= lo && cv[c] > -1.0e38f) {
                int pos = atomicAdd(&s_na, 1);
                if (pos < AMBMAX) s_ambi[pos] = ci[c];
            }
        }
        __syncthreads();
        int na = min(s_na, AMBMAX);

        // exact fp32 rescore of each ambiguous feature
        const float* xr = g_X + (size_t)row * KDIM;
        for (int j = 0; j < na; j++) {
            const float* wr = Wenc + (size_t)s_ambi[j] * KDIM;
            float part = 0.0f;
            for (int i = tid; i < KDIM; i += 256) part += xr[i] * wr[i];
            #pragma unroll
            for (int o = 16; o > 0; o >>= 1)
                part += __shfl_xor_sync(0xffffffffu, part, o);
            if ((tid & 31) == 0) s_part[tid >> 5] = part;
            __syncthreads();
            if (tid == 0) {
                float tsum = 0.0f;
                #pragma unroll
                for (int i = 0; i < 8; i++) tsum += s_part[i];
                s_ambx[j] = tsum + benc[s_ambi[j]];
            }
            __syncthreads();
        }

        // thread 0: pick top (64-m) ambiguous by (exact value, lower index)
        if (tid == 0) {
            for (int pick = 0; pick < TOPK - m; pick++) {
                int bj = -1;
                float bv = -3.0e38f; int bi = DHID;
                for (int j = 0; j < na; j++) {
                    float v = s_ambx[j]; int ix = s_ambi[j];
                    if (v > bv || (v == bv && ix < bi)) { bv = v; bi = ix; bj = j; }
                }
                s_seli[m + pick] = s_ambi[bj];
                s_rawv[m + pick] = s_ambx[bj];
                s_ambx[bj] = -3.0e38f;
            }
        }
        __syncthreads();
    }

    // ---- final writes ----
    if (tid < TOPK) {
        g_sel_idx[(size_t)row * TOPK + tid] = s_seli[tid];
        g_sel_val[(size_t)row * TOPK + tid] = fmaxf(s_rawv[tid], 0.0f);
    }
    __syncthreads();
    for (int i = tid; i < DHID; i += 256) zr[i] = 0.0f;
    __syncthreads();
    if (tid < TOPK) zr[s_seli[tid]] = fmaxf(s_rawv[tid], 0.0f);
}

// ---------------------------------------------------------------------------
// 5) Sparse decode (unchanged)
// ---------------------------------------------------------------------------
__device__ __forceinline__ void fma4(float4& acc, float v, float4 w) {
    acc.x += v * w.x; acc.y += v * w.y; acc.z += v * w.z; acc.w += v * w.w;
}

__global__ __launch_bounds__(256) void decode_kernel(float* __restrict__ rec_m,
                                                     float* __restrict__ rec_p,
                                                     int p_in_out) {
    int row = blockIdx.x, tid = threadIdx.x;
    __shared__ int   si[TOPK];
    __shared__ float sv[TOPK];
    if (tid < TOPK) {
        si[tid] = g_sel_idx[(size_t)row * TOPK + tid];
        sv[tid] = g_sel_val[(size_t)row * TOPK + tid];
    }
    __syncthreads();

    float4 am0 = {0.f, 0.f, 0.f, 0.f}, am1 = am0, ap0 = am0, ap1 = am0;

    #pragma unroll 4
    for (int j = 0; j < TOPK; j++) {
        float v = sv[j];
        size_t base = (size_t)si[j] * DIN;
        const float4* wm = (const float4*)(g_WmT + base);
        const float4* wp = (const float4*)(g_WpT + base);
        float4 a0 = wm[tid], a1 = wm[tid + 256];
        float4 b0 = wp[tid], b1 = wp[tid + 256];
        fma4(am0, v, a0); fma4(am1, v, a1);
        fma4(ap0, v, b0); fma4(ap1, v, b1);
    }

    float4* om = (float4*)(rec_m + (size_t)row * DIN);
    float* pp = p_in_out ? rec_p : g_dump;
    float4* op = (float4*)(pp + (size_t)row * DIN);
    om[tid] = am0; om[tid + 256] = am1;
    op[tid] = ap0; op[tid + 256] = ap1;
}

// ---------------------------------------------------------------------------
// Launch (by-size binding + adaptive output layout — unchanged from R9)
// ---------------------------------------------------------------------------
extern "C" void kernel_launch(void* const* d_in, const int* in_sizes, int n_in,
                              void* d_out, int out_size) {
    const float* x_m = 0; const float* x_p = 0;
    const float* W_enc = 0; const float* b_enc = 0;
    const float* W_dec_m = 0; const float* W_dec_p = 0;

    for (int i = 0; i < n_in; i++) {
        long long s = in_sizes[i];
        const float* p = (const float*)d_in[i];
        if (s == (long long)BATCH * DIN) {
            if (!x_m) x_m = p; else x_p = p;
        } else if (s == (long long)DHID * KDIM) {
            W_enc = p;
        } else if (s == (long long)DHID) {
            b_enc = p;
        } else if (s == (long long)DIN * DHID) {
            if (!W_dec_m) W_dec_m = p; else W_dec_p = p;
        }
    }
    if (!x_m || !x_p || !W_enc || !b_enc || !W_dec_m || !W_dec_p)
        return;

    const long long SZ_REC  = (long long)BATCH * DIN;
    const long long SZ_FULL = 2 * SZ_REC + (long long)BATCH * DHID;

    float* rec_m = (float*)d_out;
    float* rec_p = rec_m;
    float* z_ptr = rec_m;
    int p_in_out = 0, z_in_out = 0;

    if ((long long)out_size >= SZ_FULL) {
        rec_p = rec_m + SZ_REC; z_ptr = rec_p + SZ_REC;
        p_in_out = 1; z_in_out = 1;
    } else if ((long long)out_size >= 2 * SZ_REC) {
        rec_p = rec_m + SZ_REC;
        p_in_out = 1; z_in_out = 0;
    } else {
        p_in_out = 0; z_in_out = 0;
    }

    cudaFuncSetAttribute(gemm_kernel,
                         cudaFuncAttributeMaxDynamicSharedMemorySize, GEMM_DSMEM);

    // 1) concat + fp32 -> bf16 hi/lo splits
    split_x_kernel<<<(BATCH * (KDIM / 4)) / 256, 256>>>((const float4*)x_m,
                                                        (const float4*)x_p);
    split_w_kernel<<<(DHID * (KDIM / 4)) / 256, 256>>>((const float4*)W_enc);

    // 2) bf16 mma.sync encoder GEMM (3-term split)
    gemm_kernel<<<dim3(BATCH / 128, DHID / 128), 256, GEMM_DSMEM>>>(b_enc);

    // 3) decoder transposes
    dim3 tgrid(DHID / 32, DIN / 32), tblk(32, 8);
    transpose_kernel<<<tgrid, tblk>>>(W_dec_m, 0);
    transpose_kernel<<<tgrid, tblk>>>(W_dec_p, 1);

    // 4) top-k (with exact-fp32 boundary rescue) + z
    topk_kernel<<<BATCH, 256>>>(z_ptr, z_in_out, W_enc, b_enc);

    // 5) sparse decode
    decode_kernel<<<BATCH, 256>>>(rec_m, rec_p, p_in_out);
}

// round 17
// speedup vs baseline: 3.4574x; 1.4405x over previous
#include <cuda_runtime.h>
#include <cuda_bf16.h>
#include <cstdint>

// Problem constants (fixed shapes)
#define BATCH 4096
#define DIN   2048
#define DHID  16384
#define KDIM  4096   // 2*DIN
#define TOPK  64

// ---------------------------------------------------------------------------
// Device scratch (__device__ globals; never passed as kernel args from host)
// ---------------------------------------------------------------------------
__device__ float        g_X  [(size_t)BATCH * KDIM];   //  64 MB concat fp32 (rescue)
__device__ __nv_bfloat16 g_Ahi[(size_t)BATCH * KDIM];  //  32 MB
__device__ __nv_bfloat16 g_Alo[(size_t)BATCH * KDIM];  //  32 MB
__device__ __nv_bfloat16 g_Bhi[(size_t)DHID * KDIM];   // 128 MB (W_enc bf16; no lo term)
__device__ float g_pre[(size_t)BATCH * DHID];          // 256 MB screen out / z fallback
__device__ float g_WmT[(size_t)DHID * DIN];            // 128 MB W_dec_m^T
__device__ float g_WpT[(size_t)DHID * DIN];            // 128 MB W_dec_p^T
__device__ float g_dump[(size_t)BATCH * DIN];          //  33 MB rec_p fallback
__device__ int   g_sel_idx[(size_t)BATCH * TOPK];
__device__ float g_sel_val[(size_t)BATCH * TOPK];

// ---------------------------------------------------------------------------
// PTX helpers — family-level instructions only (compile on compute_103)
// ---------------------------------------------------------------------------
__device__ __forceinline__ uint32_t smem_u32(const void* p) {
    uint32_t a;
    asm("{ .reg .u64 t; cvta.to.shared.u64 t, %1; cvt.u32.u64 %0, t; }"
        : "=r"(a) : "l"(p));
    return a;
}

__device__ __forceinline__ void cp16(uint32_t s, const void* g) {
    asm volatile("cp.async.cg.shared.global [%0], [%1], 16;"
                 :: "r"(s), "l"(g) : "memory");
}
#define CP_COMMIT() asm volatile("cp.async.commit_group;" ::: "memory")
#define CP_WAIT1()  asm volatile("cp.async.wait_group 1;" ::: "memory")
#define CP_WAIT0()  asm volatile("cp.async.wait_group 0;" ::: "memory")

#define LDSM4(r, addr) \
    asm volatile("ldmatrix.sync.aligned.m8n8.x4.shared.b16 {%0,%1,%2,%3}, [%4];" \
        : "=r"((r)[0]), "=r"((r)[1]), "=r"((r)[2]), "=r"((r)[3]) : "r"(addr))

#define MMA16816(d, a, b0, b1) \
    asm volatile("mma.sync.aligned.m16n8k16.row.col.f32.bf16.bf16.f32 " \
        "{%0,%1,%2,%3}, {%4,%5,%6,%7}, {%8,%9}, {%0,%1,%2,%3};" \
        : "+f"((d)[0]), "+f"((d)[1]), "+f"((d)[2]), "+f"((d)[3]) \
        : "r"((a)[0]), "r"((a)[1]), "r"((a)[2]), "r"((a)[3]), "r"(b0), "r"(b1))

// ---------------------------------------------------------------------------
// 1a) concat x -> g_X (fp32, for rescue) and split into bf16 hi/lo
// ---------------------------------------------------------------------------
__global__ void split_x_kernel(const float4* __restrict__ xm,
                               const float4* __restrict__ xp) {
    int i = blockIdx.x * blockDim.x + threadIdx.x;   // BATCH*KDIM/4
    int row = i >> 10, c4 = i & 1023;
    float4 v = (c4 < 512) ? xm[(size_t)row * 512 + c4]
                          : xp[(size_t)row * 512 + (c4 - 512)];
    ((float4*)g_X)[i] = v;
    float f[4] = {v.x, v.y, v.z, v.w};
    __nv_bfloat16 hx[4], lx[4];
    #pragma unroll
    for (int j = 0; j < 4; j++) {
        hx[j] = __float2bfloat16(f[j]);
        lx[j] = __float2bfloat16(f[j] - __bfloat162float(hx[j]));
    }
    __nv_bfloat162 h0, h1, l0, l1;
    h0.x = hx[0]; h0.y = hx[1]; h1.x = hx[2]; h1.y = hx[3];
    l0.x = lx[0]; l0.y = lx[1]; l1.x = lx[2]; l1.y = lx[3];
    ((__nv_bfloat162*)g_Ahi)[2 * i] = h0; ((__nv_bfloat162*)g_Ahi)[2 * i + 1] = h1;
    ((__nv_bfloat162*)g_Alo)[2 * i] = l0; ((__nv_bfloat162*)g_Alo)[2 * i + 1] = l1;
}

// 1b) W_enc -> bf16 (hi only; w_lo term dropped, covered by rescue + EMAX)
__global__ void split_w_kernel(const float4* __restrict__ W) {
    int i = blockIdx.x * blockDim.x + threadIdx.x;   // DHID*KDIM/4
    float4 v = W[i];
    __nv_bfloat162 h0, h1;
    h0.x = __float2bfloat16(v.x); h0.y = __float2bfloat16(v.y);
    h1.x = __float2bfloat16(v.z); h1.y = __float2bfloat16(v.w);
    ((__nv_bfloat162*)g_Bhi)[2 * i] = h0;
    ((__nv_bfloat162*)g_Bhi)[2 * i + 1] = h1;
}

// ---------------------------------------------------------------------------
// 2) mma.sync bf16 GEMM, 2-term split (hh + lh), fp32 reg accumulators.
//    CTA tile 128x128, K-chunk 64, 2-stage cp.async double buffer,
//    3 smem tiles/stage (Ahi|Alo|Bhi) -> 108 KB total -> 2 CTAs/SM.
//    8 warps = 4(M) x 2(N); warp tile 32x64. Rows padded to 144B.
// ---------------------------------------------------------------------------
#define GK       64
#define NC       (KDIM / GK)              // 64 chunks
#define ROWB     144                      // 128B data + 16B pad
#define TILE_B   (128 * ROWB)             // 18432
#define STAGE_B  (3 * TILE_B)             // Ahi|Alo|Bhi = 55296
#define GEMM_DSMEM (2 * STAGE_B + 256)    // 110848

__global__ __launch_bounds__(256, 2) void gemm_kernel(const float* __restrict__ bias) {
    extern __shared__ char dsm_raw[];
    uint32_t dyn = (smem_u32(dsm_raw) + 255) & ~255u;

    const int tid  = threadIdx.x;
    const int lane = tid & 31;
    const int wid  = tid >> 5;
    const int bm   = blockIdx.x * 128;    // M (fast grid dim -> B L2 reuse)
    const int bn   = blockIdx.y * 128;    // N
    const int wm   = (wid >> 1) * 32;     // warp M offset
    const int wn   = (wid & 1) * 64;      // warp N offset

    const uint32_t aRow = (uint32_t)(wm + (lane & 15));
    const uint32_t aKo  = (uint32_t)((lane >> 4) * 16);
    const uint32_t bRow = (uint32_t)(wn + (lane & 7) + ((lane >> 4) << 3));
    const uint32_t bKo  = (uint32_t)(((lane >> 3) & 1) * 16);

    float acc[2][8][4];
    #pragma unroll
    for (int mi = 0; mi < 2; mi++)
        #pragma unroll
        for (int ni = 0; ni < 8; ni++)
            #pragma unroll
            for (int q = 0; q < 4; q++) acc[mi][ni][q] = 0.0f;

    // chunk loader: 3 tiles x 128 rows x 128B via 16B cp.async
    const int lrow = tid >> 3;      // 0..31
    const int lseg = tid & 7;       // 0..7
    auto load_chunk = [&](int c) {
        const int kc = c * GK;
        const uint32_t sb = dyn + (uint32_t)(c & 1) * STAGE_B;
        #pragma unroll
        for (int tile = 0; tile < 3; tile++) {
            const __nv_bfloat16* src =
                (tile == 0) ? g_Ahi : (tile == 1) ? g_Alo : g_Bhi;
            const int base = (tile < 2) ? bm : bn;
            #pragma unroll
            for (int p = 0; p < 4; p++) {
                const int r = lrow + p * 32;
                cp16(sb + (uint32_t)tile * TILE_B + (uint32_t)r * ROWB + (uint32_t)lseg * 16,
                     src + (size_t)(base + r) * KDIM + kc + lseg * 8);
            }
        }
        CP_COMMIT();
    };

    load_chunk(0);
    load_chunk(1);

    for (int c = 0; c < NC; c++) {
        if (c < NC - 2) CP_WAIT1(); else CP_WAIT0();
        __syncthreads();

        const uint32_t sb = dyn + (uint32_t)(c & 1) * STAGE_B;
        #pragma unroll
        for (int kk = 0; kk < 4; kk++) {
            const uint32_t kby = (uint32_t)kk * 32;
            uint32_t ah[2][4], al[2][4], bh[4][4];
            #pragma unroll
            for (int mi = 0; mi < 2; mi++) {
                uint32_t ra = sb + (aRow + (uint32_t)mi * 16) * ROWB + kby + aKo;
                LDSM4(ah[mi], ra);
                LDSM4(al[mi], ra + TILE_B);
            }
            #pragma unroll
            for (int g = 0; g < 4; g++) {
                uint32_t rb = sb + 2u * TILE_B + (bRow + (uint32_t)g * 16) * ROWB + kby + bKo;
                LDSM4(bh[g], rb);
            }
            // term hh
            #pragma unroll
            for (int mi = 0; mi < 2; mi++)
                #pragma unroll
                for (int ni = 0; ni < 8; ni++)
                    MMA16816(acc[mi][ni], ah[mi],
                             bh[ni >> 1][(ni & 1) * 2], bh[ni >> 1][(ni & 1) * 2 + 1]);
            // term lh
            #pragma unroll
            for (int mi = 0; mi < 2; mi++)
                #pragma unroll
                for (int ni = 0; ni < 8; ni++)
                    MMA16816(acc[mi][ni], al[mi],
                             bh[ni >> 1][(ni & 1) * 2], bh[ni >> 1][(ni & 1) * 2 + 1]);
        }
        __syncthreads();
        if (c + 2 < NC) load_chunk(c + 2);
    }

    // epilogue: direct float2 stores + bias
    #pragma unroll
    for (int mi = 0; mi < 2; mi++) {
        const int m0 = bm + wm + mi * 16 + (lane >> 2);
        #pragma unroll
        for (int ni = 0; ni < 8; ni++) {
            const int n = bn + wn + ni * 8 + ((lane & 3) << 1);
            const float b0 = bias[n], b1 = bias[n + 1];
            float2 v0 = make_float2(acc[mi][ni][0] + b0, acc[mi][ni][1] + b1);
            float2 v1 = make_float2(acc[mi][ni][2] + b0, acc[mi][ni][3] + b1);
            *(float2*)(g_pre + (size_t)m0 * DHID + n)       = v0;
            *(float2*)(g_pre + (size_t)(m0 + 8) * DHID + n) = v1;
        }
    }
}

// ---------------------------------------------------------------------------
// 3) Transpose W_dec [DIN, DHID] -> g_WmT / g_WpT (dest flag in device code)
// ---------------------------------------------------------------------------
__global__ void transpose_kernel(const float* __restrict__ in, int which) {
    float* out = which ? g_WpT : g_WmT;
    const int R = DIN, C = DHID;
    __shared__ float tile[32][33];
    int c0 = blockIdx.x * 32, r0 = blockIdx.y * 32;
    int tx = threadIdx.x, ty = threadIdx.y;
    #pragma unroll
    for (int j = 0; j < 32; j += 8)
        tile[ty + j][tx] = in[(size_t)(r0 + ty + j) * C + c0 + tx];
    __syncthreads();
    #pragma unroll
    for (int j = 0; j < 32; j += 8)
        out[(size_t)(c0 + ty + j) * R + r0 + tx] = tile[tx][ty + j];
}

// ---------------------------------------------------------------------------
// 4) Per-row top-64 on the SCREEN with exact-fp32 boundary rescue.
//    EMAX = 4e-3 (~7 sigma of the 2-term screen error, sigma ~ 5.6e-4).
// ---------------------------------------------------------------------------
#define CAP 2048
#define RROUNDS 65
#define EMAX 4.0e-3f
#define AMBMAX 96

__device__ __forceinline__ unsigned long long tk_pack(float v, int idx) {
    unsigned int u = __float_as_uint(v);
    u = (u & 0x80000000u) ? ~u : (u | 0x80000000u);
    return ((unsigned long long)u << 32) | (unsigned int)(DHID - 1 - idx);
}

__global__ __launch_bounds__(256) void topk_kernel(float* __restrict__ z_out,
                                                   int z_in_out,
                                                   const float* __restrict__ Wenc,
                                                   const float* __restrict__ benc) {
    int row = blockIdx.x, tid = threadIdx.x;
    const float* p = g_pre + (size_t)row * DHID;
    float* zr = (z_in_out ? z_out : g_pre) + (size_t)row * DHID;

    __shared__ float cv[CAP];
    __shared__ int   ci[CAP];
    __shared__ int   s_cnt;
    __shared__ unsigned long long s_red[8];
    __shared__ unsigned long long s_win;
    __shared__ unsigned int selmask[DHID / 32];
    __shared__ int   s_seli[RROUNDS];
    __shared__ float s_rawv[RROUNDS];
    __shared__ int   s_ambi[AMBMAX];
    __shared__ float s_ambx[AMBMAX];
    __shared__ int   s_na, s_m;
    __shared__ float s_part[8];

    const float thr[2] = {2.0f, 1.0f};
    int cnt = -1;
    for (int t = 0; t < 2; t++) {
        if (tid == 0) s_cnt = 0;
        __syncthreads();
        for (int i = tid; i < DHID; i += 256) {
            float v = p[i];
            if (v > thr[t]) {
                int pos = atomicAdd(&s_cnt, 1);
                if (pos < CAP) { cv[pos] = v; ci[pos] = i; }
            }
        }
        __syncthreads();
        cnt = s_cnt;
        __syncthreads();
        if (cnt >= RROUNDS && cnt <= CAP) break;
        if (t == 0 && cnt > CAP) { cnt = -1; break; }
    }
    bool fb = !(cnt >= RROUNDS && cnt <= CAP);
    if (fb) {
        for (int i = tid; i < DHID / 32; i += 256) selmask[i] = 0u;
        __syncthreads();
    }

    for (int r = 0; r < RROUNDS; r++) {
        unsigned long long best = 0ull;
        if (!fb) {
            for (int c = tid; c < cnt; c += 256) {
                unsigned long long k2 = tk_pack(cv[c], ci[c]);
                if (k2 > best) best = k2;
            }
        } else {
            for (int i = tid; i < DHID; i += 256) {
                if (selmask[i >> 5] & (1u << (i & 31))) continue;
                unsigned long long k2 = tk_pack(p[i], i);
                if (k2 > best) best = k2;
            }
        }
        #pragma unroll
        for (int o = 16; o > 0; o >>= 1) {
            unsigned long long other = __shfl_xor_sync(0xffffffffu, best, o);
            if (other > best) best = other;
        }
        if ((tid & 31) == 0) s_red[tid >> 5] = best;
        __syncthreads();
        if (tid == 0) {
            unsigned long long w = s_red[0];
            #pragma unroll
            for (int i = 1; i < 8; i++)
                if (s_red[i] > w) w = s_red[i];
            s_win = w;
        }
        __syncthreads();
        unsigned long long w = s_win;
        int fidx = (DHID - 1) - (int)(w & 0xffffffffull);
        if (tid == 0) {
            unsigned int u = (unsigned int)(w >> 32);
            u = (u & 0x80000000u) ? (u & 0x7fffffffu) : ~u;
            s_seli[r] = fidx;
            s_rawv[r] = __uint_as_float(u);   // raw (pre-relu) screen value
        }
        if (!fb) {
            for (int c = tid; c < cnt; c += 256)
                if (ci[c] == fidx) cv[c] = -3.0e38f;
        } else {
            if (tid == 0) selmask[fidx >> 5] |= (1u << (fidx & 31));
        }
        __syncthreads();
    }

    // ---- exactness rescue ----
    if (tid == 0) {
        float S65 = s_rawv[RROUNDS - 1];
        int m = 0;
        while (m < TOPK && s_rawv[m] > S65 + 2.0f * EMAX) m++;
        s_m = m;
    }
    __syncthreads();
    int m = s_m;

    if (!fb && m < TOPK) {
        if (tid == 0) s_na = 0;
        __syncthreads();
        float lo = s_rawv[RROUNDS - 1] - 2.0f * EMAX;
        if (tid <= (RROUNDS - 1) - m) {            // ranked m..64
            int pos = atomicAdd(&s_na, 1);
            if (pos < AMBMAX) s_ambi[pos] = s_seli[m + tid];
        }
        for (int c = tid; c < cnt; c += 256) {     // unranked near-boundary
            if (cv[c] >= lo && cv[c] > -1.0e38f) {
                int pos = atomicAdd(&s_na, 1);
                if (pos < AMBMAX) s_ambi[pos] = ci[c];
            }
        }
        __syncthreads();
        int na = min(s_na, AMBMAX);

        // exact fp32 rescore of each ambiguous feature
        const float* xr = g_X + (size_t)row * KDIM;
        for (int j = 0; j < na; j++) {
            const float* wr = Wenc + (size_t)s_ambi[j] * KDIM;
            float part = 0.0f;
            for (int i = tid; i < KDIM; i += 256) part += xr[i] * wr[i];
            #pragma unroll
            for (int o = 16; o > 0; o >>= 1)
                part += __shfl_xor_sync(0xffffffffu, part, o);
            if ((tid & 31) == 0) s_part[tid >> 5] = part;
            __syncthreads();
            if (tid == 0) {
                float tsum = 0.0f;
                #pragma unroll
                for (int i = 0; i < 8; i++) tsum += s_part[i];
                s_ambx[j] = tsum + benc[s_ambi[j]];
            }
            __syncthreads();
        }

        if (tid == 0) {
            for (int pick = 0; pick < TOPK - m; pick++) {
                int bj = -1;
                float bv = -3.0e38f; int bi = DHID;
                for (int j = 0; j < na; j++) {
                    float v = s_ambx[j]; int ix = s_ambi[j];
                    if (v > bv || (v == bv && ix < bi)) { bv = v; bi = ix; bj = j; }
                }
                s_seli[m + pick] = s_ambi[bj];
                s_rawv[m + pick] = s_ambx[bj];
                s_ambx[bj] = -3.0e38f;
            }
        }
        __syncthreads();
    }

    // ---- final writes ----
    if (tid < TOPK) {
        g_sel_idx[(size_t)row * TOPK + tid] = s_seli[tid];
        g_sel_val[(size_t)row * TOPK + tid] = fmaxf(s_rawv[tid], 0.0f);
    }
    __syncthreads();
    for (int i = tid; i < DHID; i += 256) zr[i] = 0.0f;
    __syncthreads();
    if (tid < TOPK) zr[s_seli[tid]] = fmaxf(s_rawv[tid], 0.0f);
}

// ---------------------------------------------------------------------------
// 5) Sparse decode (unchanged)
// ---------------------------------------------------------------------------
__device__ __forceinline__ void fma4(float4& acc, float v, float4 w) {
    acc.x += v * w.x; acc.y += v * w.y; acc.z += v * w.z; acc.w += v * w.w;
}

__global__ __launch_bounds__(256) void decode_kernel(float* __restrict__ rec_m,
                                                     float* __restrict__ rec_p,
                                                     int p_in_out) {
    int row = blockIdx.x, tid = threadIdx.x;
    __shared__ int   si[TOPK];
    __shared__ float sv[TOPK];
    if (tid < TOPK) {
        si[tid] = g_sel_idx[(size_t)row * TOPK + tid];
        sv[tid] = g_sel_val[(size_t)row * TOPK + tid];
    }
    __syncthreads();

    float4 am0 = {0.f, 0.f, 0.f, 0.f}, am1 = am0, ap0 = am0, ap1 = am0;

    #pragma unroll 4
    for (int j = 0; j < TOPK; j++) {
        float v = sv[j];
        size_t base = (size_t)si[j] * DIN;
        const float4* wm = (const float4*)(g_WmT + base);
        const float4* wp = (const float4*)(g_WpT + base);
        float4 a0 = wm[tid], a1 = wm[tid + 256];
        float4 b0 = wp[tid], b1 = wp[tid + 256];
        fma4(am0, v, a0); fma4(am1, v, a1);
        fma4(ap0, v, b0); fma4(ap1, v, b1);
    }

    float4* om = (float4*)(rec_m + (size_t)row * DIN);
    float* pp = p_in_out ? rec_p : g_dump;
    float4* op = (float4*)(pp + (size_t)row * DIN);
    om[tid] = am0; om[tid + 256] = am1;
    op[tid] = ap0; op[tid + 256] = ap1;
}

// ---------------------------------------------------------------------------
// Launch (by-size binding + adaptive output layout — unchanged)
// ---------------------------------------------------------------------------
extern "C" void kernel_launch(void* const* d_in, const int* in_sizes, int n_in,
                              void* d_out, int out_size) {
    const float* x_m = 0; const float* x_p = 0;
    const float* W_enc = 0; const float* b_enc = 0;
    const float* W_dec_m = 0; const float* W_dec_p = 0;

    for (int i = 0; i < n_in; i++) {
        long long s = in_sizes[i];
        const float* p = (const float*)d_in[i];
        if (s == (long long)BATCH * DIN) {
            if (!x_m) x_m = p; else x_p = p;
        } else if (s == (long long)DHID * KDIM) {
            W_enc = p;
        } else if (s == (long long)DHID) {
            b_enc = p;
        } else if (s == (long long)DIN * DHID) {
            if (!W_dec_m) W_dec_m = p; else W_dec_p = p;
        }
    }
    if (!x_m || !x_p || !W_enc || !b_enc || !W_dec_m || !W_dec_p)
        return;

    const long long SZ_REC  = (long long)BATCH * DIN;
    const long long SZ_FULL = 2 * SZ_REC + (long long)BATCH * DHID;

    float* rec_m = (float*)d_out;
    float* rec_p = rec_m;
    float* z_ptr = rec_m;
    int p_in_out = 0, z_in_out = 0;

    if ((long long)out_size >= SZ_FULL) {
        rec_p = rec_m + SZ_REC; z_ptr = rec_p + SZ_REC;
        p_in_out = 1; z_in_out = 1;
    } else if ((long long)out_size >= 2 * SZ_REC) {
        rec_p = rec_m + SZ_REC;
        p_in_out = 1; z_in_out = 0;
    } else {
        p_in_out = 0; z_in_out = 0;
    }

    cudaFuncSetAttribute(gemm_kernel,
                         cudaFuncAttributeMaxDynamicSharedMemorySize, GEMM_DSMEM);

    // 1) concat + fp32 -> bf16 splits (A hi/lo, W hi only)
    split_x_kernel<<<(BATCH * (KDIM / 4)) / 256, 256>>>((const float4*)x_m,
                                                        (const float4*)x_p);
    split_w_kernel<<<(DHID * (KDIM / 4)) / 256, 256>>>((const float4*)W_enc);

    // 2) bf16 mma.sync encoder GEMM (2-term split, 2 CTAs/SM)
    gemm_kernel<<<dim3(BATCH / 128, DHID / 128), 256, GEMM_DSMEM>>>(b_enc);

    // 3) decoder transposes
    dim3 tgrid(DHID / 32, DIN / 32), tblk(32, 8);
    transpose_kernel<<<tgrid, tblk>>>(W_dec_m, 0);
    transpose_kernel<<<tgrid, tblk>>>(W_dec_p, 1);

    // 4) top-k (with exact-fp32 boundary rescue) + z
    topk_kernel<<<BATCH, 256>>>(z_ptr, z_in_out, W_enc, b_enc);

    // 5) sparse decode
    decode_kernel<<<BATCH, 256>>>(rec_m, rec_p, p_in_out);
}